// round 1
// baseline (speedup 1.0000x reference)
#include <cuda_runtime.h>
#include <math.h>

#define Nn 8192
#define Dd 512
#define NHEADS 8
#define HDIM 64
#define TOPK 16

// ---------------- scratch (static device globals; no allocation) -------------
__device__ float g_seq[2 * Nn * Dd];          // 32 MB  [N,2,D] proj+LN output
__device__ float g_qkv[2 * Nn * 3 * Dd];      // 96 MB  [N,2,3D]
__device__ float g_ctx[2 * Nn * Dd];          // 32 MB  [N,2,D] attention ctx
__device__ float g_att[2 * Nn * Dd];          // 32 MB  [N,2,D] out-proj
__device__ float g_fused[Nn * Dd];            // 16 MB  [N,D]
__device__ float g_S[(size_t)Nn * Nn];        // 256 MB [N,N] sim logits
__device__ float g_hidden[Nn * (Dd / 2)];     // 8 MB   [N,256]

// ---------------- generic fp32 GEMM: C[m,n] = sum_k A[m,k]*B[n,k] (+bias,relu)
// A: [M,K] row-major, B: [N,K] row-major, C row-major with leading dim ldc.
// M % 128 == 0, N % 128 == 0, K % 16 == 0 (true for all call sites).
template <int RELU>
__global__ __launch_bounds__(256, 2) void gemm_nt(
    const float* __restrict__ A, const float* __restrict__ B,
    const float* __restrict__ bias, float* __restrict__ C,
    int M, int Ncols, int K, int ldc)
{
    const int BK = 16;
    __shared__ float As[BK][128 + 4];
    __shared__ float Bs[BK][128 + 4];
    const int bm = blockIdx.y * 128, bn = blockIdx.x * 128;
    const int tid = threadIdx.x;
    const int tr = (tid / 16) * 8;   // row offset of 8x8 thread tile
    const int tc = (tid % 16) * 8;   // col offset

    float acc[8][8];
#pragma unroll
    for (int i = 0; i < 8; i++)
#pragma unroll
        for (int j = 0; j < 8; j++) acc[i][j] = 0.f;

    for (int k0 = 0; k0 < K; k0 += BK) {
#pragma unroll
        for (int i = 0; i < 2; i++) {
            int slot = tid * 2 + i;           // 0..511 -> 128 rows x 4 float4
            int row = slot >> 2;
            int c4 = (slot & 3) * 4;
            float4 va = *(const float4*)(A + (size_t)(bm + row) * K + k0 + c4);
            As[c4 + 0][row] = va.x; As[c4 + 1][row] = va.y;
            As[c4 + 2][row] = va.z; As[c4 + 3][row] = va.w;
            float4 vb = *(const float4*)(B + (size_t)(bn + row) * K + k0 + c4);
            Bs[c4 + 0][row] = vb.x; Bs[c4 + 1][row] = vb.y;
            Bs[c4 + 2][row] = vb.z; Bs[c4 + 3][row] = vb.w;
        }
        __syncthreads();
#pragma unroll
        for (int k = 0; k < BK; k++) {
            float a[8], b[8];
#pragma unroll
            for (int i = 0; i < 8; i++) a[i] = As[k][tr + i];
#pragma unroll
            for (int j = 0; j < 8; j++) b[j] = Bs[k][tc + j];
#pragma unroll
            for (int i = 0; i < 8; i++)
#pragma unroll
                for (int j = 0; j < 8; j++) acc[i][j] += a[i] * b[j];
        }
        __syncthreads();
    }

#pragma unroll
    for (int i = 0; i < 8; i++) {
#pragma unroll
        for (int j = 0; j < 8; j++) {
            float v = acc[i][j];
            if (bias) v += bias[bn + tc + j];
            if (RELU) v = fmaxf(v, 0.f);
            C[(size_t)(bm + tr + i) * ldc + bn + tc + j] = v;
        }
    }
}

// ---------------- LayerNorm over last dim (in-place on g_seq rows) -----------
__global__ void ln_kernel(const float* __restrict__ g0, const float* __restrict__ be0,
                          const float* __restrict__ g1, const float* __restrict__ be1)
{
    int row = blockIdx.x;                       // token row 0..2N-1 (even=mod0)
    float* x = g_seq + (size_t)row * Dd;
    int tid = threadIdx.x;                      // 256 threads, 2 elems each
    float v0 = x[tid], v1 = x[tid + 256];
    __shared__ float rs[256], rq[256];
    rs[tid] = v0 + v1;
    rq[tid] = v0 * v0 + v1 * v1;
    __syncthreads();
    for (int st = 128; st > 0; st >>= 1) {
        if (tid < st) { rs[tid] += rs[tid + st]; rq[tid] += rq[tid + st]; }
        __syncthreads();
    }
    float mean = rs[0] * (1.f / Dd);
    float var = rq[0] * (1.f / Dd) - mean * mean;
    float inv = rsqrtf(var + 1e-5f);
    const float* gg = (row & 1) ? g1 : g0;
    const float* bb = (row & 1) ? be1 : be0;
    x[tid]       = (v0 - mean) * inv * gg[tid] + bb[tid];
    x[tid + 256] = (v1 - mean) * inv * gg[tid + 256] + bb[tid + 256];
}

// ---------------- 2-token multihead attention: one warp per (node, head) ----
__global__ void attn_kernel()
{
    int gt = blockIdx.x * blockDim.x + threadIdx.x;
    int gw = gt >> 5;
    int lane = gt & 31;
    if (gw >= Nn * NHEADS) return;
    int node = gw >> 3, h = gw & 7;
    const float* base = g_qkv + (size_t)node * 2 * (3 * Dd);
    int d0 = lane * 2;                       // 2 head-dims per lane

    float q[2][2], k[2][2], v[2][2];
#pragma unroll
    for (int t = 0; t < 2; t++) {
        const float* r = base + t * (3 * Dd) + h * HDIM;
        float2 qq = *(const float2*)(r + d0);
        float2 kk = *(const float2*)(r + Dd + d0);
        float2 vv = *(const float2*)(r + 2 * Dd + d0);
        q[t][0] = qq.x; q[t][1] = qq.y;
        k[t][0] = kk.x; k[t][1] = kk.y;
        v[t][0] = vv.x; v[t][1] = vv.y;
    }
    float s[2][2];
#pragma unroll
    for (int qi = 0; qi < 2; qi++)
#pragma unroll
        for (int ki = 0; ki < 2; ki++)
            s[qi][ki] = q[qi][0] * k[ki][0] + q[qi][1] * k[ki][1];
#pragma unroll
    for (int o = 16; o > 0; o >>= 1) {
#pragma unroll
        for (int qi = 0; qi < 2; qi++)
#pragma unroll
            for (int ki = 0; ki < 2; ki++)
                s[qi][ki] += __shfl_xor_sync(0xffffffffu, s[qi][ki], o);
    }
    const float scale = 0.125f;  // 1/sqrt(64)
#pragma unroll
    for (int qi = 0; qi < 2; qi++) {
        float a0 = s[qi][0] * scale, a1 = s[qi][1] * scale;
        float m = fmaxf(a0, a1);
        float e0 = expf(a0 - m), e1 = expf(a1 - m);
        float inv = 1.f / (e0 + e1);
        float w0 = e0 * inv, w1 = e1 * inv;
        float* o = g_ctx + (size_t)(node * 2 + qi) * Dd + h * HDIM + d0;
        o[0] = w0 * v[0][0] + w1 * v[1][0];
        o[1] = w0 * v[0][1] + w1 * v[1][1];
    }
}

// ---------------- mean over the 2 tokens -------------------------------------
__global__ void mean_kernel()
{
    int i = blockIdx.x * blockDim.x + threadIdx.x;
    if (i >= Nn * Dd) return;
    int node = i / Dd, d = i - node * Dd;
    g_fused[i] = 0.5f * (g_att[(size_t)(node * 2) * Dd + d] +
                         g_att[(size_t)(node * 2 + 1) * Dd + d]);
}

// ---------------- per-row softmax stats + top-16 + scatter into H -----------
__global__ void topk_kernel(float* __restrict__ Hout)
{
    int row = blockIdx.x;
    extern __shared__ float sh[];            // Nn floats (32 KB)
    __shared__ float red[256];
    __shared__ int redi[256];
    __shared__ float topv[TOPK];
    __shared__ int topi[TOPK];
    const float* srow = g_S + (size_t)row * Nn;
    int tid = threadIdx.x;

    float lmax = -INFINITY;
    for (int j = tid; j < Nn; j += 256) {
        float v = srow[j];
        sh[j] = v;
        lmax = fmaxf(lmax, v);
    }
    red[tid] = lmax; __syncthreads();
    for (int st = 128; st > 0; st >>= 1) {
        if (tid < st) red[tid] = fmaxf(red[tid], red[tid + st]);
        __syncthreads();
    }
    float rmax = red[0]; __syncthreads();

    float lsum = 0.f;
    for (int j = tid; j < Nn; j += 256) lsum += expf(sh[j] - rmax);
    red[tid] = lsum; __syncthreads();
    for (int st = 128; st > 0; st >>= 1) {
        if (tid < st) red[tid] += red[tid + st];
        __syncthreads();
    }
    float rinv = 1.f / red[0]; __syncthreads();

    for (int kk = 0; kk < TOPK; kk++) {
        float lm = -INFINITY; int li = 0x7fffffff;
        for (int j = tid; j < Nn; j += 256) {
            float v = sh[j];
            if (v > lm) { lm = v; li = j; }
        }
        red[tid] = lm; redi[tid] = li; __syncthreads();
        for (int st = 128; st > 0; st >>= 1) {
            if (tid < st) {
                if (red[tid + st] > red[tid] ||
                    (red[tid + st] == red[tid] && redi[tid + st] < redi[tid])) {
                    red[tid] = red[tid + st]; redi[tid] = redi[tid + st];
                }
            }
            __syncthreads();
        }
        if (tid == 0) {
            topv[kk] = red[0];
            topi[kk] = redi[0];
            sh[redi[0]] = -INFINITY;         // remove winner
        }
        __syncthreads();
    }

    if (tid == 0) {
        // diag first, then scatter column `row` (same thread -> ordered,
        // matching the JAX overwrite semantics). Writes are conflict-free
        // across blocks: block i is the sole writer of column i.
        Hout[(size_t)row * Nn + row] = 1.0f;
#pragma unroll
        for (int kk = 0; kk < TOPK; kk++)
            Hout[(size_t)topi[kk] * Nn + row] = expf(topv[kk] - rmax) * rinv;
    }
}

// ---------------- edge-weight head: sigmoid(hidden @ w2 + b2) ----------------
__global__ void ew_kernel(const float* __restrict__ w2, const float* __restrict__ b2,
                          float* __restrict__ out)
{
    int gt = blockIdx.x * blockDim.x + threadIdx.x;
    int gw = gt >> 5, lane = gt & 31;
    if (gw >= Nn) return;
    const float* hrow = g_hidden + (size_t)gw * (Dd / 2);
    float s = 0.f;
    for (int j = lane; j < Dd / 2; j += 32) s += hrow[j] * w2[j];
#pragma unroll
    for (int o = 16; o > 0; o >>= 1) s += __shfl_xor_sync(0xffffffffu, s, o);
    if (lane == 0) {
        float v = s + b2[0];
        float sig = 1.f / (1.f + expf(-v));
        out[gw] = fmaxf(sig, 1e-8f);
    }
}

// ---------------- launch ------------------------------------------------------
extern "C" void kernel_launch(void* const* d_in, const int* in_sizes, int n_in,
                              void* d_out, int out_size)
{
    const float* x0    = (const float*)d_in[0];
    const float* x1    = (const float*)d_in[1];
    const float* w_p0  = (const float*)d_in[2];
    const float* b_p0  = (const float*)d_in[3];
    const float* gg0   = (const float*)d_in[4];
    const float* be0   = (const float*)d_in[5];
    const float* w_p1  = (const float*)d_in[6];
    const float* b_p1  = (const float*)d_in[7];
    const float* gg1   = (const float*)d_in[8];
    const float* be1   = (const float*)d_in[9];
    const float* in_w  = (const float*)d_in[10];
    const float* in_b  = (const float*)d_in[11];
    const float* out_w = (const float*)d_in[12];
    const float* out_b = (const float*)d_in[13];
    const float* ew_w1 = (const float*)d_in[14];
    const float* ew_b1 = (const float*)d_in[15];
    const float* ew_w2 = (const float*)d_in[16];
    const float* ew_b2 = (const float*)d_in[17];

    float* H  = (float*)d_out;
    float* ew = H + (size_t)Nn * Nn;

    float *seq, *qkv, *ctx, *att, *fused, *S, *hidden;
    cudaGetSymbolAddress((void**)&seq, g_seq);
    cudaGetSymbolAddress((void**)&qkv, g_qkv);
    cudaGetSymbolAddress((void**)&ctx, g_ctx);
    cudaGetSymbolAddress((void**)&att, g_att);
    cudaGetSymbolAddress((void**)&fused, g_fused);
    cudaGetSymbolAddress((void**)&S, g_S);
    cudaGetSymbolAddress((void**)&hidden, g_hidden);

    // Zero H (the only touched H entries are diag + scatter; rest must be 0).
    cudaMemsetAsync(H, 0, (size_t)Nn * Nn * sizeof(float));

    dim3 thr(256);

    // 1) per-modality projection (Linear + bias + ReLU) into interleaved seq
    gemm_nt<1><<<dim3(Dd / 128, Nn / 128), thr>>>(x0, w_p0, b_p0, seq,      Nn, Dd, Dd, 2 * Dd);
    gemm_nt<1><<<dim3(Dd / 128, Nn / 128), thr>>>(x1, w_p1, b_p1, seq + Dd, Nn, Dd, Dd, 2 * Dd);

    // 2) LayerNorm per token row (in place)
    ln_kernel<<<2 * Nn, 256>>>(gg0, be0, gg1, be1);

    // 3) packed qkv projection
    gemm_nt<0><<<dim3(3 * Dd / 128, 2 * Nn / 128), thr>>>(seq, in_w, in_b, qkv, 2 * Nn, 3 * Dd, Dd, 3 * Dd);

    // 4) 2-token attention
    attn_kernel<<<(Nn * NHEADS * 32) / 256, 256>>>();

    // 5) out-proj (+bias)
    gemm_nt<0><<<dim3(Dd / 128, 2 * Nn / 128), thr>>>(ctx, out_w, out_b, att, 2 * Nn, Dd, Dd, Dd);

    // 6) fuse (mean over 2 tokens)
    mean_kernel<<<(Nn * Dd) / 256, 256>>>();

    // 7) similarity logits S = fused @ fused^T
    gemm_nt<0><<<dim3(Nn / 128, Nn / 128), thr>>>(fused, fused, nullptr, S, Nn, Nn, Dd, Nn);

    // 8) row softmax stats + top-16 + scatter into H
    topk_kernel<<<Nn, 256, Nn * sizeof(float)>>>(H);

    // 9) edge-weight MLP
    gemm_nt<1><<<dim3((Dd / 2) / 128, Nn / 128), thr>>>(fused, ew_w1, ew_b1, hidden, Nn, Dd / 2, Dd, Dd / 2);
    ew_kernel<<<(Nn * 32) / 256, 256>>>(ew_w2, ew_b2, ew);
}

// round 4
// speedup vs baseline: 2.5260x; 2.5260x over previous
#include <cuda_runtime.h>
#include <cuda_bf16.h>
#include <math.h>
#include <stdint.h>

#define Nn 8192
#define Dd 512
#define KDIM 512
#define NHEADS 8
#define HDIM 64
#define TOPK 16

// ---------------- scratch (static device globals; no allocation) -------------
__device__ float g_seq[2 * Nn * Dd];
__device__ float g_qkv[2 * Nn * 3 * Dd];
__device__ float g_ctx[2 * Nn * Dd];
__device__ float g_att[2 * Nn * Dd];
__device__ float g_fused[Nn * Dd];
__device__ float g_S[(size_t)Nn * Nn];
__device__ float g_hidden[Nn * (Dd / 2)];
__device__ uint16_t g_ah[2 * Nn * Dd], g_al[2 * Nn * Dd];   // activations hi/lo
__device__ uint16_t g_bh[3 * Dd * Dd], g_bl[3 * Dd * Dd];   // weights hi/lo
__device__ uint16_t g_fh[Nn * Dd], g_fl[Nn * Dd];           // fused hi/lo

// ============================ PTX helpers ====================================
__device__ __forceinline__ uint32_t smem_u32(const void* p) {
    uint32_t a;
    asm("{ .reg .u64 t; cvta.to.shared.u64 t, %1; cvt.u32.u64 %0, t; }" : "=r"(a) : "l"(p));
    return a;
}
__device__ __forceinline__ void cp16(uint32_t dst, const void* src) {
    asm volatile("cp.async.cg.shared.global [%0], [%1], 16;" :: "r"(dst), "l"(src) : "memory");
}
__device__ __forceinline__ void cp_commit() {
    asm volatile("cp.async.commit_group;" ::: "memory");
}
template <int N> __device__ __forceinline__ void cp_wait() {
    asm volatile("cp.async.wait_group %0;" :: "n"(N) : "memory");
}
__device__ __forceinline__ void ldsm4(uint32_t* r, uint32_t a) {
    asm volatile("ldmatrix.sync.aligned.m8n8.x4.shared.b16 {%0,%1,%2,%3}, [%4];"
                 : "=r"(r[0]), "=r"(r[1]), "=r"(r[2]), "=r"(r[3]) : "r"(a));
}
__device__ __forceinline__ void mma16816(float* c, const uint32_t* a, uint32_t b0, uint32_t b1) {
    asm volatile("mma.sync.aligned.m16n8k16.row.col.f32.bf16.bf16.f32 "
                 "{%0,%1,%2,%3}, {%4,%5,%6,%7}, {%8,%9}, {%0,%1,%2,%3};"
                 : "+f"(c[0]), "+f"(c[1]), "+f"(c[2]), "+f"(c[3])
                 : "r"(a[0]), "r"(a[1]), "r"(a[2]), "r"(a[3]), "r"(b0), "r"(b1));
}

// ======================= warp-MMA NT GEMM (bf16 hi/lo, fp32 acc) =============
// C[M,N] = sum over 3 passes: Ah*Bh^T, Ah*Bl^T, Al*Bh^T.  K == 512 everywhere.
// Tile 128x128, BK=32 (64B rows), double-buffered cp.async, swizzled ldmatrix.
// Swizzle: 16B chunk c of row r lives at  r*64 + ((c ^ ((r>>1)&3))<<4).
template <int RELU, int HAS_BIAS>
__global__ __launch_bounds__(256, 2) void tgemm(
    const uint16_t* __restrict__ Ahp, const uint16_t* __restrict__ Alp,
    const uint16_t* __restrict__ Bhp, const uint16_t* __restrict__ Blp,
    const float* __restrict__ bias, float* __restrict__ C, int ldc)
{
    __shared__ uint16_t sA[2][128 * 32];
    __shared__ uint16_t sB[2][128 * 32];

    const int tid = threadIdx.x;
    const int lane = tid & 31, wid = tid >> 5;
    const int wm = wid & 3;          // 4 warps over M (32 rows each)
    const int wn = wid >> 2;         // 2 warps over N (64 cols each)
    const int bm = blockIdx.y * 128, bn = blockIdx.x * 128;

    const uint32_t sa0 = smem_u32(&sA[0][0]), sa1 = smem_u32(&sA[1][0]);
    const uint32_t sb0 = smem_u32(&sB[0][0]), sb1 = smem_u32(&sB[1][0]);

    const uint16_t* Asrc[3] = { Ahp, Ahp, Alp };
    const uint16_t* Bsrc[3] = { Bhp, Blp, Bhp };
    const int CPP = KDIM / 32;       // 16 chunks per pass
    const int NCHK = 3 * CPP;        // 48

    // per-thread loader geometry: 2 chunks16 per thread per matrix
    uint32_t lsw[2]; size_t lsrc[2];
    {
#pragma unroll
        for (int i = 0; i < 2; i++) {
            int s = tid + 256 * i;               // 0..511
            int r = s >> 2, c = s & 3;
            lsw[i] = r * 64 + (((c ^ ((r >> 1) & 3))) << 4);
            lsrc[i] = (size_t)r * KDIM + c * 8;
        }
    }

    // ldmatrix address offsets (within a buffer)
    uint32_t offA[2][2], offB[2][4];
#pragma unroll
    for (int kk = 0; kk < 2; kk++) {
#pragma unroll
        for (int f = 0; f < 2; f++) {
            int r = wm * 32 + f * 16 + (lane & 15);
            int c = kk * 2 + (lane >> 4);
            offA[kk][f] = r * 64 + (((c ^ ((r >> 1) & 3))) << 4);
        }
#pragma unroll
        for (int g = 0; g < 4; g++) {
            int r = wn * 64 + g * 16 + (lane & 7) + ((lane >> 4) << 3);
            int c = kk * 2 + ((lane >> 3) & 1);
            offB[kk][g] = r * 64 + (((c ^ ((r >> 1) & 3))) << 4);
        }
    }

    float acc[2][8][4];
#pragma unroll
    for (int f = 0; f < 2; f++)
#pragma unroll
        for (int g = 0; g < 8; g++)
#pragma unroll
            for (int j = 0; j < 4; j++) acc[f][g][j] = 0.f;

    auto load_chunk = [&](int c, int buf) {
        const int pass = c / CPP;
        const int k0 = (c % CPP) * 32;
        const uint16_t* A = Asrc[pass];
        const uint16_t* B = Bsrc[pass];
        const uint32_t da = buf ? sa1 : sa0;
        const uint32_t db = buf ? sb1 : sb0;
#pragma unroll
        for (int i = 0; i < 2; i++) {
            cp16(da + lsw[i], A + (size_t)bm * KDIM + k0 + lsrc[i]);
            cp16(db + lsw[i], B + (size_t)bn * KDIM + k0 + lsrc[i]);
        }
        cp_commit();
    };

    load_chunk(0, 0);

    for (int c = 0; c < NCHK; c++) {
        const int b = c & 1;
        if (c + 1 < NCHK) { load_chunk(c + 1, b ^ 1); cp_wait<1>(); }
        else cp_wait<0>();
        __syncthreads();

        const uint32_t da = b ? sa1 : sa0;
        const uint32_t db = b ? sb1 : sb0;
#pragma unroll
        for (int kk = 0; kk < 2; kk++) {
            uint32_t ra[2][4], rb[4][4];
#pragma unroll
            for (int f = 0; f < 2; f++) ldsm4(ra[f], da + offA[kk][f]);
#pragma unroll
            for (int g = 0; g < 4; g++) ldsm4(rb[g], db + offB[kk][g]);
#pragma unroll
            for (int f = 0; f < 2; f++)
#pragma unroll
                for (int g = 0; g < 4; g++) {
                    mma16816(acc[f][2 * g + 0], ra[f], rb[g][0], rb[g][1]);
                    mma16816(acc[f][2 * g + 1], ra[f], rb[g][2], rb[g][3]);
                }
        }
        __syncthreads();
    }

    // epilogue: direct fp32 stores (float2), optional bias/relu
    const int col0 = bn + wn * 64 + (lane & 3) * 2;
#pragma unroll
    for (int f = 0; f < 2; f++) {
        const int row0 = bm + wm * 32 + f * 16 + (lane >> 2);
#pragma unroll
        for (int g = 0; g < 8; g++) {
            const int col = col0 + g * 8;
            float b0 = 0.f, b1 = 0.f;
            if (HAS_BIAS) { b0 = bias[col]; b1 = bias[col + 1]; }
            float2 v0, v1;
            v0.x = acc[f][g][0] + b0; v0.y = acc[f][g][1] + b1;
            v1.x = acc[f][g][2] + b0; v1.y = acc[f][g][3] + b1;
            if (RELU) {
                v0.x = fmaxf(v0.x, 0.f); v0.y = fmaxf(v0.y, 0.f);
                v1.x = fmaxf(v1.x, 0.f); v1.y = fmaxf(v1.y, 0.f);
            }
            *(float2*)(C + (size_t)row0 * ldc + col) = v0;
            *(float2*)(C + (size_t)(row0 + 8) * ldc + col) = v1;
        }
    }
}

// ---------------- fp32 -> (hi, lo) bf16 split --------------------------------
__global__ void split_kernel(const float* __restrict__ x, uint16_t* __restrict__ hi,
                             uint16_t* __restrict__ lo, int n4)
{
    int i = blockIdx.x * blockDim.x + threadIdx.x;
    if (i >= n4) return;
    float4 v = ((const float4*)x)[i];
    __nv_bfloat16 h0 = __float2bfloat16(v.x), h1 = __float2bfloat16(v.y);
    __nv_bfloat16 h2 = __float2bfloat16(v.z), h3 = __float2bfloat16(v.w);
    __nv_bfloat16 l0 = __float2bfloat16(v.x - __bfloat162float(h0));
    __nv_bfloat16 l1 = __float2bfloat16(v.y - __bfloat162float(h1));
    __nv_bfloat16 l2 = __float2bfloat16(v.z - __bfloat162float(h2));
    __nv_bfloat16 l3 = __float2bfloat16(v.w - __bfloat162float(h3));
    ushort4 hv, lv;
    hv.x = __bfloat16_as_ushort(h0); hv.y = __bfloat16_as_ushort(h1);
    hv.z = __bfloat16_as_ushort(h2); hv.w = __bfloat16_as_ushort(h3);
    lv.x = __bfloat16_as_ushort(l0); lv.y = __bfloat16_as_ushort(l1);
    lv.z = __bfloat16_as_ushort(l2); lv.w = __bfloat16_as_ushort(l3);
    ((ushort4*)hi)[i] = hv;
    ((ushort4*)lo)[i] = lv;
}

// ---------------- LayerNorm over last dim (in-place on g_seq rows) -----------
__global__ void ln_kernel(const float* __restrict__ g0, const float* __restrict__ be0,
                          const float* __restrict__ g1, const float* __restrict__ be1)
{
    int row = blockIdx.x;
    float* x = g_seq + (size_t)row * Dd;
    int tid = threadIdx.x;
    float v0 = x[tid], v1 = x[tid + 256];
    __shared__ float rs[256], rq[256];
    rs[tid] = v0 + v1;
    rq[tid] = v0 * v0 + v1 * v1;
    __syncthreads();
    for (int st = 128; st > 0; st >>= 1) {
        if (tid < st) { rs[tid] += rs[tid + st]; rq[tid] += rq[tid + st]; }
        __syncthreads();
    }
    float mean = rs[0] * (1.f / Dd);
    float var = rq[0] * (1.f / Dd) - mean * mean;
    float inv = rsqrtf(var + 1e-5f);
    const float* gg = (row & 1) ? g1 : g0;
    const float* bb = (row & 1) ? be1 : be0;
    x[tid]       = (v0 - mean) * inv * gg[tid] + bb[tid];
    x[tid + 256] = (v1 - mean) * inv * gg[tid + 256] + bb[tid + 256];
}

// ---------------- 2-token multihead attention --------------------------------
__global__ void attn_kernel()
{
    int gt = blockIdx.x * blockDim.x + threadIdx.x;
    int gw = gt >> 5, lane = gt & 31;
    if (gw >= Nn * NHEADS) return;
    int node = gw >> 3, h = gw & 7;
    const float* base = g_qkv + (size_t)node * 2 * (3 * Dd);
    int d0 = lane * 2;
    float q[2][2], k[2][2], v[2][2];
#pragma unroll
    for (int t = 0; t < 2; t++) {
        const float* r = base + t * (3 * Dd) + h * HDIM;
        float2 qq = *(const float2*)(r + d0);
        float2 kk = *(const float2*)(r + Dd + d0);
        float2 vv = *(const float2*)(r + 2 * Dd + d0);
        q[t][0] = qq.x; q[t][1] = qq.y;
        k[t][0] = kk.x; k[t][1] = kk.y;
        v[t][0] = vv.x; v[t][1] = vv.y;
    }
    float s[2][2];
#pragma unroll
    for (int qi = 0; qi < 2; qi++)
#pragma unroll
        for (int ki = 0; ki < 2; ki++)
            s[qi][ki] = q[qi][0] * k[ki][0] + q[qi][1] * k[ki][1];
#pragma unroll
    for (int o = 16; o > 0; o >>= 1)
#pragma unroll
        for (int qi = 0; qi < 2; qi++)
#pragma unroll
            for (int ki = 0; ki < 2; ki++)
                s[qi][ki] += __shfl_xor_sync(0xffffffffu, s[qi][ki], o);
    const float scale = 0.125f;
#pragma unroll
    for (int qi = 0; qi < 2; qi++) {
        float a0 = s[qi][0] * scale, a1 = s[qi][1] * scale;
        float m = fmaxf(a0, a1);
        float e0 = expf(a0 - m), e1 = expf(a1 - m);
        float inv = 1.f / (e0 + e1);
        float w0 = e0 * inv, w1 = e1 * inv;
        float* o = g_ctx + (size_t)(node * 2 + qi) * Dd + h * HDIM + d0;
        o[0] = w0 * v[0][0] + w1 * v[1][0];
        o[1] = w0 * v[0][1] + w1 * v[1][1];
    }
}

__global__ void mean_kernel()
{
    int i = blockIdx.x * blockDim.x + threadIdx.x;
    if (i >= Nn * Dd) return;
    int node = i / Dd, d = i - node * Dd;
    g_fused[i] = 0.5f * (g_att[(size_t)(node * 2) * Dd + d] +
                         g_att[(size_t)(node * 2 + 1) * Dd + d]);
}

// ---------------- per-row softmax stats + top-16 + scatter into H -----------
__global__ void topk_kernel(float* __restrict__ Hout)
{
    int row = blockIdx.x;
    extern __shared__ float sh[];
    __shared__ float red[256];
    __shared__ int redi[256];
    __shared__ float topv[TOPK];
    __shared__ int topi[TOPK];
    const float* srow = g_S + (size_t)row * Nn;
    int tid = threadIdx.x;

    float lmax = -INFINITY;
    for (int j = tid; j < Nn; j += 256) {
        float v = srow[j];
        sh[j] = v;
        lmax = fmaxf(lmax, v);
    }
    red[tid] = lmax; __syncthreads();
    for (int st = 128; st > 0; st >>= 1) {
        if (tid < st) red[tid] = fmaxf(red[tid], red[tid + st]);
        __syncthreads();
    }
    float rmax = red[0]; __syncthreads();

    float lsum = 0.f;
    for (int j = tid; j < Nn; j += 256) lsum += expf(sh[j] - rmax);
    red[tid] = lsum; __syncthreads();
    for (int st = 128; st > 0; st >>= 1) {
        if (tid < st) red[tid] += red[tid + st];
        __syncthreads();
    }
    float rinv = 1.f / red[0]; __syncthreads();

    for (int kk = 0; kk < TOPK; kk++) {
        float lm = -INFINITY; int li = 0x7fffffff;
        for (int j = tid; j < Nn; j += 256) {
            float v = sh[j];
            if (v > lm) { lm = v; li = j; }
        }
        red[tid] = lm; redi[tid] = li; __syncthreads();
        for (int st = 128; st > 0; st >>= 1) {
            if (tid < st) {
                if (red[tid + st] > red[tid] ||
                    (red[tid + st] == red[tid] && redi[tid + st] < redi[tid])) {
                    red[tid] = red[tid + st]; redi[tid] = redi[tid + st];
                }
            }
            __syncthreads();
        }
        if (tid == 0) {
            topv[kk] = red[0];
            topi[kk] = redi[0];
            sh[redi[0]] = -INFINITY;
        }
        __syncthreads();
    }

    if (tid == 0) {
        Hout[(size_t)row * Nn + row] = 1.0f;
#pragma unroll
        for (int kk = 0; kk < TOPK; kk++)
            Hout[(size_t)topi[kk] * Nn + row] = expf(topv[kk] - rmax) * rinv;
    }
}

__global__ void ew_kernel(const float* __restrict__ w2, const float* __restrict__ b2,
                          float* __restrict__ out)
{
    int gt = blockIdx.x * blockDim.x + threadIdx.x;
    int gw = gt >> 5, lane = gt & 31;
    if (gw >= Nn) return;
    const float* hrow = g_hidden + (size_t)gw * (Dd / 2);
    float s = 0.f;
    for (int j = lane; j < Dd / 2; j += 32) s += hrow[j] * w2[j];
#pragma unroll
    for (int o = 16; o > 0; o >>= 1) s += __shfl_xor_sync(0xffffffffu, s, o);
    if (lane == 0) {
        float v = s + b2[0];
        float sig = 1.f / (1.f + expf(-v));
        out[gw] = fmaxf(sig, 1e-8f);
    }
}

// ---------------- launch ------------------------------------------------------
static void do_split(const float* src, uint16_t* hi, uint16_t* lo, size_t n)
{
    int n4 = (int)(n / 4);
    split_kernel<<<(n4 + 255) / 256, 256>>>(src, hi, lo, n4);
}

extern "C" void kernel_launch(void* const* d_in, const int* in_sizes, int n_in,
                              void* d_out, int out_size)
{
    const float* x0    = (const float*)d_in[0];
    const float* x1    = (const float*)d_in[1];
    const float* w_p0  = (const float*)d_in[2];
    const float* b_p0  = (const float*)d_in[3];
    const float* gg0   = (const float*)d_in[4];
    const float* be0   = (const float*)d_in[5];
    const float* w_p1  = (const float*)d_in[6];
    const float* b_p1  = (const float*)d_in[7];
    const float* gg1   = (const float*)d_in[8];
    const float* be1   = (const float*)d_in[9];
    const float* in_w  = (const float*)d_in[10];
    const float* in_b  = (const float*)d_in[11];
    const float* out_w = (const float*)d_in[12];
    const float* out_b = (const float*)d_in[13];
    const float* ew_w1 = (const float*)d_in[14];
    const float* ew_b1 = (const float*)d_in[15];
    const float* ew_w2 = (const float*)d_in[16];
    const float* ew_b2 = (const float*)d_in[17];

    float* H  = (float*)d_out;
    float* ew = H + (size_t)Nn * Nn;

    float *seq, *qkv, *att, *fused, *S, *hidden, *ctx;
    uint16_t *ah, *al, *bh, *bl, *fh, *fl;
    cudaGetSymbolAddress((void**)&seq, g_seq);
    cudaGetSymbolAddress((void**)&qkv, g_qkv);
    cudaGetSymbolAddress((void**)&ctx, g_ctx);
    cudaGetSymbolAddress((void**)&att, g_att);
    cudaGetSymbolAddress((void**)&fused, g_fused);
    cudaGetSymbolAddress((void**)&S, g_S);
    cudaGetSymbolAddress((void**)&hidden, g_hidden);
    cudaGetSymbolAddress((void**)&ah, g_ah);
    cudaGetSymbolAddress((void**)&al, g_al);
    cudaGetSymbolAddress((void**)&bh, g_bh);
    cudaGetSymbolAddress((void**)&bl, g_bl);
    cudaGetSymbolAddress((void**)&fh, g_fh);
    cudaGetSymbolAddress((void**)&fl, g_fl);

    cudaMemsetAsync(H, 0, (size_t)Nn * Nn * sizeof(float));

    // 1) modality projections: Linear+bias+ReLU, interleaved into seq
    do_split(x0, ah, al, (size_t)Nn * Dd);
    do_split(w_p0, bh, bl, (size_t)Dd * Dd);
    tgemm<1, 1><<<dim3(Dd / 128, Nn / 128), 256>>>(ah, al, bh, bl, b_p0, seq, 2 * Dd);
    do_split(x1, ah, al, (size_t)Nn * Dd);
    do_split(w_p1, bh, bl, (size_t)Dd * Dd);
    tgemm<1, 1><<<dim3(Dd / 128, Nn / 128), 256>>>(ah, al, bh, bl, b_p1, seq + Dd, 2 * Dd);

    // 2) LayerNorm (in place, fp32)
    ln_kernel<<<2 * Nn, 256>>>(gg0, be0, gg1, be1);

    // 3) qkv projection
    do_split(seq, ah, al, (size_t)2 * Nn * Dd);
    do_split(in_w, bh, bl, (size_t)3 * Dd * Dd);
    tgemm<0, 1><<<dim3(3 * Dd / 128, 2 * Nn / 128), 256>>>(ah, al, bh, bl, in_b, qkv, 3 * Dd);

    // 4) 2-token attention
    attn_kernel<<<(Nn * NHEADS * 32) / 256, 256>>>();

    // 5) out-proj
    do_split(ctx, ah, al, (size_t)2 * Nn * Dd);
    do_split(out_w, bh, bl, (size_t)Dd * Dd);
    tgemm<0, 1><<<dim3(Dd / 128, 2 * Nn / 128), 256>>>(ah, al, bh, bl, out_b, att, Dd);

    // 6) fuse (mean over 2 tokens)
    mean_kernel<<<(Nn * Dd) / 256, 256>>>();

    // 7) similarity logits S = fused @ fused^T
    do_split(fused, fh, fl, (size_t)Nn * Dd);
    tgemm<0, 0><<<dim3(Nn / 128, Nn / 128), 256>>>(fh, fl, fh, fl, nullptr, S, Nn);

    // 8) row softmax + top-16 + scatter
    topk_kernel<<<Nn, 256, Nn * sizeof(float)>>>(H);

    // 9) edge-weight MLP
    do_split(ew_w1, bh, bl, (size_t)(Dd / 2) * Dd);
    tgemm<1, 1><<<dim3((Dd / 2) / 128, Nn / 128), 256>>>(fh, fl, bh, bl, ew_b1, hidden, Dd / 2);
    ew_kernel<<<(Nn * 32) / 256, 256>>>(ew_w2, ew_b2, ew);
}

// round 5
// speedup vs baseline: 3.0177x; 1.1947x over previous
#include <cuda_runtime.h>
#include <cuda_bf16.h>
#include <math.h>
#include <stdint.h>

#define Nn 8192
#define Dd 512
#define KDIM 512
#define NHEADS 8
#define HDIM 64
#define TOPK 16

// ---------------- scratch (static device globals; no allocation) -------------
__device__ float g_seq[2 * Nn * Dd];
__device__ float g_qkv[2 * Nn * 3 * Dd];
__device__ float g_att[2 * Nn * Dd];
__device__ float g_S[(size_t)Nn * Nn];
__device__ float g_hidden[Nn * (Dd / 2)];
__device__ uint16_t g_ah[2 * Nn * Dd], g_al[2 * Nn * Dd];   // activations hi/lo
__device__ uint16_t g_bh[3 * Dd * Dd], g_bl[3 * Dd * Dd];   // weights hi/lo
__device__ uint16_t g_fh[Nn * Dd], g_fl[Nn * Dd];           // fused hi/lo

// ============================ PTX helpers ====================================
__device__ __forceinline__ uint32_t smem_u32(const void* p) {
    uint32_t a;
    asm("{ .reg .u64 t; cvta.to.shared.u64 t, %1; cvt.u32.u64 %0, t; }" : "=r"(a) : "l"(p));
    return a;
}
__device__ __forceinline__ void cp16(uint32_t dst, const void* src) {
    asm volatile("cp.async.cg.shared.global [%0], [%1], 16;" :: "r"(dst), "l"(src) : "memory");
}
__device__ __forceinline__ void cp_commit() {
    asm volatile("cp.async.commit_group;" ::: "memory");
}
template <int N> __device__ __forceinline__ void cp_wait() {
    asm volatile("cp.async.wait_group %0;" :: "n"(N) : "memory");
}
__device__ __forceinline__ void ldsm4(uint32_t* r, uint32_t a) {
    asm volatile("ldmatrix.sync.aligned.m8n8.x4.shared.b16 {%0,%1,%2,%3}, [%4];"
                 : "=r"(r[0]), "=r"(r[1]), "=r"(r[2]), "=r"(r[3]) : "r"(a));
}
__device__ __forceinline__ void mma16816(float* c, const uint32_t* a, uint32_t b0, uint32_t b1) {
    asm volatile("mma.sync.aligned.m16n8k16.row.col.f32.bf16.bf16.f32 "
                 "{%0,%1,%2,%3}, {%4,%5,%6,%7}, {%8,%9}, {%0,%1,%2,%3};"
                 : "+f"(c[0]), "+f"(c[1]), "+f"(c[2]), "+f"(c[3])
                 : "r"(a[0]), "r"(a[1]), "r"(a[2]), "r"(a[3]), "r"(b0), "r"(b1));
}

// ======================= warp-MMA NT GEMM (bf16 hi/lo, fp32 acc) =============
// C[M,N] = sum over 3 passes: Ah*Bh^T, Ah*Bl^T, Al*Bh^T.  K == 512 everywhere.
// Tile 128x128, BK=32 (64B rows), double-buffered cp.async, swizzled ldmatrix.
template <int RELU, int HAS_BIAS>
__global__ __launch_bounds__(256, 2) void tgemm(
    const uint16_t* __restrict__ Ahp, const uint16_t* __restrict__ Alp,
    const uint16_t* __restrict__ Bhp, const uint16_t* __restrict__ Blp,
    const float* __restrict__ bias, float* __restrict__ C, int ldc)
{
    __shared__ uint16_t sA[2][128 * 32];
    __shared__ uint16_t sB[2][128 * 32];

    const int tid = threadIdx.x;
    const int lane = tid & 31, wid = tid >> 5;
    const int wm = wid & 3;
    const int wn = wid >> 2;
    const int bm = blockIdx.y * 128, bn = blockIdx.x * 128;

    const uint32_t sa0 = smem_u32(&sA[0][0]), sa1 = smem_u32(&sA[1][0]);
    const uint32_t sb0 = smem_u32(&sB[0][0]), sb1 = smem_u32(&sB[1][0]);

    const uint16_t* Asrc[3] = { Ahp, Ahp, Alp };
    const uint16_t* Bsrc[3] = { Bhp, Blp, Bhp };
    const int CPP = KDIM / 32;
    const int NCHK = 3 * CPP;

    uint32_t lsw[2]; size_t lsrc[2];
#pragma unroll
    for (int i = 0; i < 2; i++) {
        int s = tid + 256 * i;
        int r = s >> 2, c = s & 3;
        lsw[i] = r * 64 + (((c ^ ((r >> 1) & 3))) << 4);
        lsrc[i] = (size_t)r * KDIM + c * 8;
    }

    uint32_t offA[2][2], offB[2][4];
#pragma unroll
    for (int kk = 0; kk < 2; kk++) {
#pragma unroll
        for (int f = 0; f < 2; f++) {
            int r = wm * 32 + f * 16 + (lane & 15);
            int c = kk * 2 + (lane >> 4);
            offA[kk][f] = r * 64 + (((c ^ ((r >> 1) & 3))) << 4);
        }
#pragma unroll
        for (int g = 0; g < 4; g++) {
            int r = wn * 64 + g * 16 + (lane & 7) + ((lane >> 4) << 3);
            int c = kk * 2 + ((lane >> 3) & 1);
            offB[kk][g] = r * 64 + (((c ^ ((r >> 1) & 3))) << 4);
        }
    }

    float acc[2][8][4];
#pragma unroll
    for (int f = 0; f < 2; f++)
#pragma unroll
        for (int g = 0; g < 8; g++)
#pragma unroll
            for (int j = 0; j < 4; j++) acc[f][g][j] = 0.f;

    auto load_chunk = [&](int c, int buf) {
        const int pass = c / CPP;
        const int k0 = (c % CPP) * 32;
        const uint16_t* A = Asrc[pass];
        const uint16_t* B = Bsrc[pass];
        const uint32_t da = buf ? sa1 : sa0;
        const uint32_t db = buf ? sb1 : sb0;
#pragma unroll
        for (int i = 0; i < 2; i++) {
            cp16(da + lsw[i], A + (size_t)bm * KDIM + k0 + lsrc[i]);
            cp16(db + lsw[i], B + (size_t)bn * KDIM + k0 + lsrc[i]);
        }
        cp_commit();
    };

    load_chunk(0, 0);

    for (int c = 0; c < NCHK; c++) {
        const int b = c & 1;
        if (c + 1 < NCHK) { load_chunk(c + 1, b ^ 1); cp_wait<1>(); }
        else cp_wait<0>();
        __syncthreads();

        const uint32_t da = b ? sa1 : sa0;
        const uint32_t db = b ? sb1 : sb0;
#pragma unroll
        for (int kk = 0; kk < 2; kk++) {
            uint32_t ra[2][4], rb[4][4];
#pragma unroll
            for (int f = 0; f < 2; f++) ldsm4(ra[f], da + offA[kk][f]);
#pragma unroll
            for (int g = 0; g < 4; g++) ldsm4(rb[g], db + offB[kk][g]);
#pragma unroll
            for (int f = 0; f < 2; f++)
#pragma unroll
                for (int g = 0; g < 4; g++) {
                    mma16816(acc[f][2 * g + 0], ra[f], rb[g][0], rb[g][1]);
                    mma16816(acc[f][2 * g + 1], ra[f], rb[g][2], rb[g][3]);
                }
        }
        __syncthreads();
    }

    const int col0 = bn + wn * 64 + (lane & 3) * 2;
#pragma unroll
    for (int f = 0; f < 2; f++) {
        const int row0 = bm + wm * 32 + f * 16 + (lane >> 2);
#pragma unroll
        for (int g = 0; g < 8; g++) {
            const int col = col0 + g * 8;
            float b0 = 0.f, b1 = 0.f;
            if (HAS_BIAS) { b0 = bias[col]; b1 = bias[col + 1]; }
            float2 v0, v1;
            v0.x = acc[f][g][0] + b0; v0.y = acc[f][g][1] + b1;
            v1.x = acc[f][g][2] + b0; v1.y = acc[f][g][3] + b1;
            if (RELU) {
                v0.x = fmaxf(v0.x, 0.f); v0.y = fmaxf(v0.y, 0.f);
                v1.x = fmaxf(v1.x, 0.f); v1.y = fmaxf(v1.y, 0.f);
            }
            *(float2*)(C + (size_t)row0 * ldc + col) = v0;
            *(float2*)(C + (size_t)(row0 + 8) * ldc + col) = v1;
        }
    }
}

// ============== symmetric variant: S = F*F^T, upper-triangle blocks ==========
// grid.x = 2080 (bi<=bj); computes tile (bi,bj), writes it and (if bi!=bj)
// the mirrored tile via an smem-staged transpose (coalesced).
__global__ __launch_bounds__(256, 2) void tgemm_sym(
    const uint16_t* __restrict__ Fh, const uint16_t* __restrict__ Fl,
    float* __restrict__ C)
{
    __shared__ __align__(16) uint8_t smraw[32768];
    uint16_t* sAbase = (uint16_t*)smraw;                 // 2 bufs x 8KB
    uint16_t* sBbase = (uint16_t*)(smraw + 16384);       // 2 bufs x 8KB
    float* smT = (float*)smraw;                          // reused in epilogue

    const int tid = threadIdx.x;
    const int lane = tid & 31, wid = tid >> 5;
    const int wm = wid & 3;
    const int wn = wid >> 2;

    int t = blockIdx.x;
    int bj = (int)((sqrtf(8.f * t + 1.f) - 1.f) * 0.5f);
    while ((bj + 1) * (bj + 2) / 2 <= t) bj++;
    while (bj * (bj + 1) / 2 > t) bj--;
    int bi = t - bj * (bj + 1) / 2;
    const int bm = bi * 128, bn = bj * 128;

    const uint32_t sa0 = smem_u32(sAbase), sa1 = smem_u32(sAbase + 4096);
    const uint32_t sb0 = smem_u32(sBbase), sb1 = smem_u32(sBbase + 4096);

    const uint16_t* Asrc[3] = { Fh, Fh, Fl };
    const uint16_t* Bsrc[3] = { Fh, Fl, Fh };
    const int CPP = KDIM / 32;
    const int NCHK = 3 * CPP;

    uint32_t lsw[2]; size_t lsrc[2];
#pragma unroll
    for (int i = 0; i < 2; i++) {
        int s = tid + 256 * i;
        int r = s >> 2, c = s & 3;
        lsw[i] = r * 64 + (((c ^ ((r >> 1) & 3))) << 4);
        lsrc[i] = (size_t)r * KDIM + c * 8;
    }

    uint32_t offA[2][2], offB[2][4];
#pragma unroll
    for (int kk = 0; kk < 2; kk++) {
#pragma unroll
        for (int f = 0; f < 2; f++) {
            int r = wm * 32 + f * 16 + (lane & 15);
            int c = kk * 2 + (lane >> 4);
            offA[kk][f] = r * 64 + (((c ^ ((r >> 1) & 3))) << 4);
        }
#pragma unroll
        for (int g = 0; g < 4; g++) {
            int r = wn * 64 + g * 16 + (lane & 7) + ((lane >> 4) << 3);
            int c = kk * 2 + ((lane >> 3) & 1);
            offB[kk][g] = r * 64 + (((c ^ ((r >> 1) & 3))) << 4);
        }
    }

    float acc[2][8][4];
#pragma unroll
    for (int f = 0; f < 2; f++)
#pragma unroll
        for (int g = 0; g < 8; g++)
#pragma unroll
            for (int j = 0; j < 4; j++) acc[f][g][j] = 0.f;

    auto load_chunk = [&](int c, int buf) {
        const int pass = c / CPP;
        const int k0 = (c % CPP) * 32;
        const uint16_t* A = Asrc[pass];
        const uint16_t* B = Bsrc[pass];
        const uint32_t da = buf ? sa1 : sa0;
        const uint32_t db = buf ? sb1 : sb0;
#pragma unroll
        for (int i = 0; i < 2; i++) {
            cp16(da + lsw[i], A + (size_t)bm * KDIM + k0 + lsrc[i]);
            cp16(db + lsw[i], B + (size_t)bn * KDIM + k0 + lsrc[i]);
        }
        cp_commit();
    };

    load_chunk(0, 0);

    for (int c = 0; c < NCHK; c++) {
        const int b = c & 1;
        if (c + 1 < NCHK) { load_chunk(c + 1, b ^ 1); cp_wait<1>(); }
        else cp_wait<0>();
        __syncthreads();

        const uint32_t da = b ? sa1 : sa0;
        const uint32_t db = b ? sb1 : sb0;
#pragma unroll
        for (int kk = 0; kk < 2; kk++) {
            uint32_t ra[2][4], rb[4][4];
#pragma unroll
            for (int f = 0; f < 2; f++) ldsm4(ra[f], da + offA[kk][f]);
#pragma unroll
            for (int g = 0; g < 4; g++) ldsm4(rb[g], db + offB[kk][g]);
#pragma unroll
            for (int f = 0; f < 2; f++)
#pragma unroll
                for (int g = 0; g < 4; g++) {
                    mma16816(acc[f][2 * g + 0], ra[f], rb[g][0], rb[g][1]);
                    mma16816(acc[f][2 * g + 1], ra[f], rb[g][2], rb[g][3]);
                }
        }
        __syncthreads();
    }

    // normal (upper) tile write
    const int col0 = bn + wn * 64 + (lane & 3) * 2;
#pragma unroll
    for (int f = 0; f < 2; f++) {
        const int row0 = bm + wm * 32 + f * 16 + (lane >> 2);
#pragma unroll
        for (int g = 0; g < 8; g++) {
            const int col = col0 + g * 8;
            float2 v0, v1;
            v0.x = acc[f][g][0]; v0.y = acc[f][g][1];
            v1.x = acc[f][g][2]; v1.y = acc[f][g][3];
            *(float2*)(C + (size_t)row0 * Nn + col) = v0;
            *(float2*)(C + (size_t)(row0 + 8) * Nn + col) = v1;
        }
    }

    // mirrored (lower) tile write via smem transpose, coalesced
    if (bi != bj) {
#pragma unroll
        for (int cc = 0; cc < 2; cc++) {
            __syncthreads();
            // stage: each wn half stages its 32 cols of this half into its buffer
            float* buf = smT + wn * (32 * 128);
#pragma unroll
            for (int gl = 0; gl < 4; gl++) {
                const int g = cc * 4 + gl;
                const int cl = gl * 8 + (lane & 3) * 2;   // local col 0..31
#pragma unroll
                for (int f = 0; f < 2; f++) {
                    const int r = wm * 32 + f * 16 + (lane >> 2);
                    buf[cl * 128 + r]           = acc[f][g][0];
                    buf[(cl + 1) * 128 + r]     = acc[f][g][1];
                    buf[cl * 128 + r + 8]       = acc[f][g][2];
                    buf[(cl + 1) * 128 + r + 8] = acc[f][g][3];
                }
            }
            __syncthreads();
            // write out 64 transposed rows (2 bufs x 32 cols), 128 floats each
            for (int idx = tid; idx < 64 * 32; idx += 256) {
                const int rr = idx >> 5;        // 0..63
                const int sg = idx & 31;        // float4 segment
                const int b2 = rr >> 5;         // which buffer (wn half)
                const int cl = rr & 31;
                const int cAbs = bn + b2 * 64 + cc * 32 + cl;
                float4 v = *(float4*)(smT + b2 * (32 * 128) + cl * 128 + sg * 4);
                *(float4*)(C + (size_t)cAbs * Nn + bm + sg * 4) = v;
            }
        }
    }
}

// ---------------- fp32 -> (hi, lo) bf16 split --------------------------------
__global__ void split_kernel(const float* __restrict__ x, uint16_t* __restrict__ hi,
                             uint16_t* __restrict__ lo, int n4)
{
    int i = blockIdx.x * blockDim.x + threadIdx.x;
    if (i >= n4) return;
    float4 v = ((const float4*)x)[i];
    __nv_bfloat16 h0 = __float2bfloat16(v.x), h1 = __float2bfloat16(v.y);
    __nv_bfloat16 h2 = __float2bfloat16(v.z), h3 = __float2bfloat16(v.w);
    __nv_bfloat16 l0 = __float2bfloat16(v.x - __bfloat162float(h0));
    __nv_bfloat16 l1 = __float2bfloat16(v.y - __bfloat162float(h1));
    __nv_bfloat16 l2 = __float2bfloat16(v.z - __bfloat162float(h2));
    __nv_bfloat16 l3 = __float2bfloat16(v.w - __bfloat162float(h3));
    ushort4 hv, lv;
    hv.x = __bfloat16_as_ushort(h0); hv.y = __bfloat16_as_ushort(h1);
    hv.z = __bfloat16_as_ushort(h2); hv.w = __bfloat16_as_ushort(h3);
    lv.x = __bfloat16_as_ushort(l0); lv.y = __bfloat16_as_ushort(l1);
    lv.z = __bfloat16_as_ushort(l2); lv.w = __bfloat16_as_ushort(l3);
    ((ushort4*)hi)[i] = hv;
    ((ushort4*)lo)[i] = lv;
}

// ---------------- LayerNorm -> bf16 hi/lo directly ---------------------------
__global__ void ln_kernel(const float* __restrict__ g0, const float* __restrict__ be0,
                          const float* __restrict__ g1, const float* __restrict__ be1)
{
    int row = blockIdx.x;
    const float* x = g_seq + (size_t)row * Dd;
    int tid = threadIdx.x;
    float v0 = x[tid], v1 = x[tid + 256];
    __shared__ float rs[256], rq[256];
    rs[tid] = v0 + v1;
    rq[tid] = v0 * v0 + v1 * v1;
    __syncthreads();
    for (int st = 128; st > 0; st >>= 1) {
        if (tid < st) { rs[tid] += rs[tid + st]; rq[tid] += rq[tid + st]; }
        __syncthreads();
    }
    float mean = rs[0] * (1.f / Dd);
    float var = rq[0] * (1.f / Dd) - mean * mean;
    float inv = rsqrtf(var + 1e-5f);
    const float* gg = (row & 1) ? g1 : g0;
    const float* bb = (row & 1) ? be1 : be0;
    float y0 = (v0 - mean) * inv * gg[tid] + bb[tid];
    float y1 = (v1 - mean) * inv * gg[tid + 256] + bb[tid + 256];
    size_t base = (size_t)row * Dd;
    __nv_bfloat16 h0 = __float2bfloat16(y0), h1 = __float2bfloat16(y1);
    g_ah[base + tid]       = __bfloat16_as_ushort(h0);
    g_ah[base + tid + 256] = __bfloat16_as_ushort(h1);
    g_al[base + tid]       = __bfloat16_as_ushort(__float2bfloat16(y0 - __bfloat162float(h0)));
    g_al[base + tid + 256] = __bfloat16_as_ushort(__float2bfloat16(y1 - __bfloat162float(h1)));
}

// ---------------- 2-token multihead attention -> ctx hi/lo -------------------
__global__ void attn_kernel()
{
    int gt = blockIdx.x * blockDim.x + threadIdx.x;
    int gw = gt >> 5, lane = gt & 31;
    if (gw >= Nn * NHEADS) return;
    int node = gw >> 3, h = gw & 7;
    const float* base = g_qkv + (size_t)node * 2 * (3 * Dd);
    int d0 = lane * 2;
    float q[2][2], k[2][2], v[2][2];
#pragma unroll
    for (int t = 0; t < 2; t++) {
        const float* r = base + t * (3 * Dd) + h * HDIM;
        float2 qq = *(const float2*)(r + d0);
        float2 kk = *(const float2*)(r + Dd + d0);
        float2 vv = *(const float2*)(r + 2 * Dd + d0);
        q[t][0] = qq.x; q[t][1] = qq.y;
        k[t][0] = kk.x; k[t][1] = kk.y;
        v[t][0] = vv.x; v[t][1] = vv.y;
    }
    float s[2][2];
#pragma unroll
    for (int qi = 0; qi < 2; qi++)
#pragma unroll
        for (int ki = 0; ki < 2; ki++)
            s[qi][ki] = q[qi][0] * k[ki][0] + q[qi][1] * k[ki][1];
#pragma unroll
    for (int o = 16; o > 0; o >>= 1)
#pragma unroll
        for (int qi = 0; qi < 2; qi++)
#pragma unroll
            for (int ki = 0; ki < 2; ki++)
                s[qi][ki] += __shfl_xor_sync(0xffffffffu, s[qi][ki], o);
    const float scale = 0.125f;
#pragma unroll
    for (int qi = 0; qi < 2; qi++) {
        float a0 = s[qi][0] * scale, a1 = s[qi][1] * scale;
        float m = fmaxf(a0, a1);
        float e0 = expf(a0 - m), e1 = expf(a1 - m);
        float inv = 1.f / (e0 + e1);
        float w0 = e0 * inv, w1 = e1 * inv;
        float o0 = w0 * v[0][0] + w1 * v[1][0];
        float o1 = w0 * v[0][1] + w1 * v[1][1];
        size_t off = (size_t)(node * 2 + qi) * Dd + h * HDIM + d0;
        __nv_bfloat16 h0 = __float2bfloat16(o0), h1 = __float2bfloat16(o1);
        ushort2 hv, lv;
        hv.x = __bfloat16_as_ushort(h0); hv.y = __bfloat16_as_ushort(h1);
        lv.x = __bfloat16_as_ushort(__float2bfloat16(o0 - __bfloat162float(h0)));
        lv.y = __bfloat16_as_ushort(__float2bfloat16(o1 - __bfloat162float(h1)));
        *(ushort2*)(g_ah + off) = hv;
        *(ushort2*)(g_al + off) = lv;
    }
}

// ---------------- mean over the 2 tokens -> fused hi/lo ----------------------
__global__ void mean_kernel()
{
    int i = blockIdx.x * blockDim.x + threadIdx.x;   // float4 index
    if (i >= Nn * Dd / 4) return;
    int e0 = i * 4;
    int node = e0 / Dd, d = e0 - node * Dd;
    const float* r0 = g_att + (size_t)(node * 2) * Dd + d;
    const float* r1 = g_att + (size_t)(node * 2 + 1) * Dd + d;
    float4 a = *(const float4*)r0, b = *(const float4*)r1;
    float f0 = 0.5f * (a.x + b.x), f1 = 0.5f * (a.y + b.y);
    float f2 = 0.5f * (a.z + b.z), f3 = 0.5f * (a.w + b.w);
    __nv_bfloat16 h0 = __float2bfloat16(f0), h1 = __float2bfloat16(f1);
    __nv_bfloat16 h2 = __float2bfloat16(f2), h3 = __float2bfloat16(f3);
    ushort4 hv, lv;
    hv.x = __bfloat16_as_ushort(h0); hv.y = __bfloat16_as_ushort(h1);
    hv.z = __bfloat16_as_ushort(h2); hv.w = __bfloat16_as_ushort(h3);
    lv.x = __bfloat16_as_ushort(__float2bfloat16(f0 - __bfloat162float(h0)));
    lv.y = __bfloat16_as_ushort(__float2bfloat16(f1 - __bfloat162float(h1)));
    lv.z = __bfloat16_as_ushort(__float2bfloat16(f2 - __bfloat162float(h2)));
    lv.w = __bfloat16_as_ushort(__float2bfloat16(f3 - __bfloat162float(h3)));
    ((ushort4*)g_fh)[i] = hv;
    ((ushort4*)g_fl)[i] = lv;
}

// ---------------- per-row softmax stats + top-16 + scatter into H -----------
__global__ void topk_kernel(float* __restrict__ Hout)
{
    int row = blockIdx.x;
    extern __shared__ float sh[];
    __shared__ float red[256];
    __shared__ int redi[256];
    __shared__ float topv[TOPK];
    __shared__ int topi[TOPK];
    const float* srow = g_S + (size_t)row * Nn;
    int tid = threadIdx.x;

    float lmax = -INFINITY;
    for (int j = tid; j < Nn; j += 256) {
        float v = srow[j];
        sh[j] = v;
        lmax = fmaxf(lmax, v);
    }
    red[tid] = lmax; __syncthreads();
    for (int st = 128; st > 0; st >>= 1) {
        if (tid < st) red[tid] = fmaxf(red[tid], red[tid + st]);
        __syncthreads();
    }
    float rmax = red[0]; __syncthreads();

    float lsum = 0.f;
    for (int j = tid; j < Nn; j += 256) lsum += expf(sh[j] - rmax);
    red[tid] = lsum; __syncthreads();
    for (int st = 128; st > 0; st >>= 1) {
        if (tid < st) red[tid] += red[tid + st];
        __syncthreads();
    }
    float rinv = 1.f / red[0]; __syncthreads();

    for (int kk = 0; kk < TOPK; kk++) {
        float lm = -INFINITY; int li = 0x7fffffff;
        for (int j = tid; j < Nn; j += 256) {
            float v = sh[j];
            if (v > lm) { lm = v; li = j; }
        }
        red[tid] = lm; redi[tid] = li; __syncthreads();
        for (int st = 128; st > 0; st >>= 1) {
            if (tid < st) {
                if (red[tid + st] > red[tid] ||
                    (red[tid + st] == red[tid] && redi[tid + st] < redi[tid])) {
                    red[tid] = red[tid + st]; redi[tid] = redi[tid + st];
                }
            }
            __syncthreads();
        }
        if (tid == 0) {
            topv[kk] = red[0];
            topi[kk] = redi[0];
            sh[redi[0]] = -INFINITY;
        }
        __syncthreads();
    }

    if (tid == 0) {
        Hout[(size_t)row * Nn + row] = 1.0f;
#pragma unroll
        for (int kk = 0; kk < TOPK; kk++)
            Hout[(size_t)topi[kk] * Nn + row] = expf(topv[kk] - rmax) * rinv;
    }
}

__global__ void ew_kernel(const float* __restrict__ w2, const float* __restrict__ b2,
                          float* __restrict__ out)
{
    int gt = blockIdx.x * blockDim.x + threadIdx.x;
    int gw = gt >> 5, lane = gt & 31;
    if (gw >= Nn) return;
    const float* hrow = g_hidden + (size_t)gw * (Dd / 2);
    float s = 0.f;
    for (int j = lane; j < Dd / 2; j += 32) s += hrow[j] * w2[j];
#pragma unroll
    for (int o = 16; o > 0; o >>= 1) s += __shfl_xor_sync(0xffffffffu, s, o);
    if (lane == 0) {
        float v = s + b2[0];
        float sig = 1.f / (1.f + expf(-v));
        out[gw] = fmaxf(sig, 1e-8f);
    }
}

// ---------------- launch ------------------------------------------------------
static void do_split(const float* src, uint16_t* hi, uint16_t* lo, size_t n)
{
    int n4 = (int)(n / 4);
    split_kernel<<<(n4 + 255) / 256, 256>>>(src, hi, lo, n4);
}

extern "C" void kernel_launch(void* const* d_in, const int* in_sizes, int n_in,
                              void* d_out, int out_size)
{
    const float* x0    = (const float*)d_in[0];
    const float* x1    = (const float*)d_in[1];
    const float* w_p0  = (const float*)d_in[2];
    const float* b_p0  = (const float*)d_in[3];
    const float* gg0   = (const float*)d_in[4];
    const float* be0   = (const float*)d_in[5];
    const float* w_p1  = (const float*)d_in[6];
    const float* b_p1  = (const float*)d_in[7];
    const float* gg1   = (const float*)d_in[8];
    const float* be1   = (const float*)d_in[9];
    const float* in_w  = (const float*)d_in[10];
    const float* in_b  = (const float*)d_in[11];
    const float* out_w = (const float*)d_in[12];
    const float* out_b = (const float*)d_in[13];
    const float* ew_w1 = (const float*)d_in[14];
    const float* ew_b1 = (const float*)d_in[15];
    const float* ew_w2 = (const float*)d_in[16];
    const float* ew_b2 = (const float*)d_in[17];

    float* H  = (float*)d_out;
    float* ew = H + (size_t)Nn * Nn;

    float *seq, *qkv, *att, *S, *hidden;
    uint16_t *ah, *al, *bh, *bl, *fh, *fl;
    cudaGetSymbolAddress((void**)&seq, g_seq);
    cudaGetSymbolAddress((void**)&qkv, g_qkv);
    cudaGetSymbolAddress((void**)&att, g_att);
    cudaGetSymbolAddress((void**)&S, g_S);
    cudaGetSymbolAddress((void**)&hidden, g_hidden);
    cudaGetSymbolAddress((void**)&ah, g_ah);
    cudaGetSymbolAddress((void**)&al, g_al);
    cudaGetSymbolAddress((void**)&bh, g_bh);
    cudaGetSymbolAddress((void**)&bl, g_bl);
    cudaGetSymbolAddress((void**)&fh, g_fh);
    cudaGetSymbolAddress((void**)&fl, g_fl);

    cudaMemsetAsync(H, 0, (size_t)Nn * Nn * sizeof(float));

    // 1) modality projections: Linear+bias+ReLU, interleaved into seq (fp32)
    do_split(x0, ah, al, (size_t)Nn * Dd);
    do_split(w_p0, bh, bl, (size_t)Dd * Dd);
    tgemm<1, 1><<<dim3(Dd / 128, Nn / 128), 256>>>(ah, al, bh, bl, b_p0, seq, 2 * Dd);
    do_split(x1, ah, al, (size_t)Nn * Dd);
    do_split(w_p1, bh, bl, (size_t)Dd * Dd);
    tgemm<1, 1><<<dim3(Dd / 128, Nn / 128), 256>>>(ah, al, bh, bl, b_p1, seq + Dd, 2 * Dd);

    // 2) LayerNorm -> ah/al (bf16 hi/lo) directly
    ln_kernel<<<2 * Nn, 256>>>(gg0, be0, gg1, be1);

    // 3) qkv projection (A = LN output hi/lo)
    do_split(in_w, bh, bl, (size_t)3 * Dd * Dd);
    tgemm<0, 1><<<dim3(3 * Dd / 128, 2 * Nn / 128), 256>>>(ah, al, bh, bl, in_b, qkv, 3 * Dd);

    // 4) 2-token attention -> ctx hi/lo into ah/al (reuse)
    attn_kernel<<<(Nn * NHEADS * 32) / 256, 256>>>();

    // 5) out-proj
    do_split(out_w, bh, bl, (size_t)Dd * Dd);
    tgemm<0, 1><<<dim3(Dd / 128, 2 * Nn / 128), 256>>>(ah, al, bh, bl, out_b, att, Dd);

    // 6) fuse (mean over 2 tokens) -> fh/fl directly
    mean_kernel<<<(Nn * Dd / 4 + 255) / 256, 256>>>();

    // 7) similarity logits S = fused @ fused^T  (symmetric: upper blocks only)
    tgemm_sym<<<(Nn / 128) * (Nn / 128 + 1) / 2, 256>>>(fh, fl, S);

    // 8) row softmax + top-16 + scatter
    topk_kernel<<<Nn, 256, Nn * sizeof(float)>>>(H);

    // 9) edge-weight MLP
    do_split(ew_w1, bh, bl, (size_t)(Dd / 2) * Dd);
    tgemm<1, 1><<<dim3((Dd / 2) / 128, Nn / 128), 256>>>(fh, fl, bh, bl, ew_b1, hidden, Dd / 2);
    ew_kernel<<<(Nn * 32) / 256, 256>>>(ew_w2, ew_b2, ew);
}